// round 12
// baseline (speedup 1.0000x reference)
#include <cuda_runtime.h>
#include <cstdint>

// Problem: x (8,512,64,64) f32, mask (64,64) i32, out (8,768,64,64) f32
#define HW      4096
#define BATCH   8
#define CIN     512
#define C2      256
#define COUT    768

#define N_MERGED HW                // 4096 CTAs: argmax row=bid + copy plane=bid
#define N_SHIFT  (BATCH * C2)      // 2048 shift planes
#define GRID_TOTAL (N_MERGED + N_SHIFT)

// Scratch (allocation-free rule: __device__ globals)
__device__ int g_sidx[HW];         // flag[i] ? nb[i] : -1
__device__ int g_done    = 0;      // merged CTAs that published their row
__device__ int g_arrived = 0;      // shift CTAs past the spin

// ---------------------------------------------------------------------------
// threefry2x32 with key (0, 42), counters (x0=0, x1=c). JAX partitionable path:
// bits[i] = o0 ^ o1 with counter = i. ks = [0, 42, 0 ^ 42 ^ 0x1BD11BDA].
// Returns the 23-bit monotone proxy for uniform(float).
// ---------------------------------------------------------------------------
__device__ __forceinline__ unsigned threefry_bits(unsigned c) {
    const unsigned ks1 = 42u;
    const unsigned ks2 = 0x1BD11BDAu ^ 42u;   // 0x1BD11BF0
    unsigned x0 = 0u;          // counts_hi + ks0
    unsigned x1 = c + ks1;     // counts_lo + ks1
#define TF_RND(r) { x0 += x1; x1 = __funnelshift_l(x1, x1, (r)); x1 ^= x0; }
    TF_RND(13) TF_RND(15) TF_RND(26) TF_RND(6)
    x0 += ks1;  x1 += ks2 + 1u;
    TF_RND(17) TF_RND(29) TF_RND(16) TF_RND(24)
    x0 += ks2;  x1 += 0u  + 2u;
    TF_RND(13) TF_RND(15) TF_RND(26) TF_RND(6)
    x0 += 0u;   x1 += ks1 + 3u;
    TF_RND(17) TF_RND(29) TF_RND(16) TF_RND(24)
    x0 += ks1;  x1 += ks2 + 4u;
    TF_RND(13) TF_RND(15) TF_RND(26) TF_RND(6)
    x0 += ks2;  x1 += 0u  + 5u;
#undef TF_RND
    return (x0 ^ x1) >> 9;
}

// ---------------------------------------------------------------------------
// Copy of plane `bid`: out[b, ch] = x[b, ch] for ch < 512.
// ---------------------------------------------------------------------------
__device__ __forceinline__ void do_copy(int bid, int tid,
                                        const float* __restrict__ x,
                                        float* __restrict__ out) {
    const int b  = bid >> 9;             // /512
    const int ch = bid & 511;
    const float4* __restrict__ src =
        (const float4*)(x + ((size_t)b * CIN + ch) * HW);
    float4* __restrict__ dst =
        (float4*)(out + ((size_t)b * COUT + ch) * HW);
#pragma unroll
    for (int k = 0; k < 4; k++) {
        int idx = tid + k * 256;
        dst[idx] = src[idx];
    }
}

// ---------------------------------------------------------------------------
// Argmax for row = bid; publishes g_sidx[row] and bumps g_done.
// ---------------------------------------------------------------------------
__device__ __forceinline__ void do_argmax(int row, int tid,
                                          const int* __restrict__ mask,
                                          unsigned* scnt, int* wred,
                                          unsigned long long* wmax) {
    const unsigned rowbase = (unsigned)row * (unsigned)HW;
    if (mask[row] > 0) {
        // ---- per-CTA ordered compaction: thread t owns cols [16t,16t+16) ----
        const int lane = tid & 31;
        const int warp = tid >> 5;
        const unsigned base = rowbase + (unsigned)(tid * 16);
        unsigned flags = 0;
        const int4* m4 = (const int4*)mask;
#pragma unroll
        for (int k = 0; k < 4; k++) {
            int4 v = m4[tid * 4 + k];
            if (v.x <= 0) flags |= 1u << (k * 4 + 0);
            if (v.y <= 0) flags |= 1u << (k * 4 + 1);
            if (v.z <= 0) flags |= 1u << (k * 4 + 2);
            if (v.w <= 0) flags |= 1u << (k * 4 + 3);
        }
        const int cnt = __popc(flags);
        int inc = cnt;
#pragma unroll
        for (int o = 1; o < 32; o <<= 1) {
            int v = __shfl_up_sync(0xFFFFFFFFu, inc, o);
            if (lane >= o) inc += v;
        }
        if (lane == 31) wred[warp] = inc;
        __syncthreads();
        if (tid < 32) {
            int v = (tid < 8) ? wred[tid] : 0;
#pragma unroll
            for (int o = 1; o < 8; o <<= 1) {
                int u = __shfl_up_sync(0xFFFFFFFFu, v, o);
                if (lane >= o) v += u;
            }
            if (tid < 8) wred[tid] = v;   // inclusive warp totals
        }
        __syncthreads();
        int pos = inc - cnt + (warp ? wred[warp - 1] : 0);
        const int m = wred[7];
#pragma unroll
        for (int k = 0; k < 16; k++) {
            if (flags & (1u << k)) scnt[pos++] = base + (unsigned)k;
        }
        __syncthreads();

        // ---- masked argmax over compacted counters ----
        unsigned bv = 0u;
        unsigned bc = rowbase + (unsigned)(HW - 1);  // phantom: loses always

        int t = tid;
        for (; t + 256 < m; t += 512) {      // two independent chains
            unsigned c0 = scnt[t];
            unsigned c1 = scnt[t + 256];
            unsigned v0 = threefry_bits(c0);
            unsigned v1 = threefry_bits(c1);
            if (v0 > bv) { bv = v0; bc = c0; }   // c0 < c1: order preserved
            if (v1 > bv) { bv = v1; bc = c1; }
        }
        if (t < m) {
            unsigned c = scnt[t];
            unsigned v = threefry_bits(c);
            if (v > bv) { bv = v; bc = c; }
        }

        const int bj = (int)(bc - rowbase);
        unsigned long long key =
            ((unsigned long long)bv << 12) | (unsigned)(HW - 1 - bj);
#pragma unroll
        for (int o = 16; o > 0; o >>= 1) {
            unsigned long long other = __shfl_xor_sync(0xFFFFFFFFu, key, o);
            if (other > key) key = other;
        }
        if ((tid & 31) == 0) wmax[tid >> 5] = key;
        __syncthreads();
        if (tid < 32) {
            unsigned long long k2 = (tid < 8) ? wmax[tid] : 0ull;
#pragma unroll
            for (int o = 4; o > 0; o >>= 1) {
                unsigned long long other = __shfl_xor_sync(0xFFFFFFFFu, k2, o);
                if (other > k2) k2 = other;
            }
            if (tid == 0) {
                g_sidx[row] = (m == 0) ? 0 : (HW - 1 - (int)(k2 & 0xFFFu));
                __threadfence();
                atomicAdd(&g_done, 1);
            }
        }
    } else {
        // dead row: nb never consumed
        if (tid == 0) {
            g_sidx[row] = -1;
            __threadfence();
            atomicAdd(&g_done, 1);
        }
    }
}

// ---------------------------------------------------------------------------
// Single fused kernel with phase staggering:
//   bid < 4096, even : copy plane=bid, then argmax row=bid
//   bid < 4096, odd  : argmax row=bid, then copy plane=bid
//     -> at any instant ~half the resident CTAs stream memory while the other
//        half grind threefry, keeping DRAM and the ALU pipes busy together.
//   bid >= 4096      : shift plane; spin on g_done.
// ---------------------------------------------------------------------------
__global__ void __launch_bounds__(256) fused_kernel(const float* __restrict__ x,
                                                    const int*   __restrict__ mask,
                                                    float*       __restrict__ out) {
    const int bid = blockIdx.x;
    const int tid = threadIdx.x;

    if (bid < N_MERGED) {
        __shared__ unsigned scnt[HW];  // rowbase + compacted column (ascending)
        __shared__ int wred[8];
        __shared__ unsigned long long wmax[8];

        const bool copy_first = (bid & 1);
        if (copy_first) do_copy(bid, tid, x, out);
        do_argmax(bid, tid, mask, scnt, wred, wmax);
        if (!copy_first) do_copy(bid, tid, x, out);
    } else {
        // ================= shift CTA =================
        const int p  = bid - N_MERGED;       // 0..2047
        const int b  = p >> 8;
        const int cc = p & 255;

        if (tid == 0) {
            // spin until every merged CTA has published its g_sidx entry.
            while (atomicAdd(&g_done, 0) != N_MERGED) __nanosleep(200);
            // the LAST shift CTA to pass the spin resets counters for the
            // next graph replay (all others already observed the condition).
            int a = atomicAdd(&g_arrived, 1);
            if (a == N_SHIFT - 1) {
                atomicExch(&g_done, 0);
                atomicExch(&g_arrived, 0);
            }
        }
        __syncthreads();

        const float* __restrict__ src = x + ((size_t)b * CIN + C2 + cc) * HW;
        float4* __restrict__ dst =
            (float4*)(out + ((size_t)b * COUT + CIN + cc) * HW);
        const int4* __restrict__ sidx4 = (const int4*)g_sidx;
#pragma unroll
        for (int k = 0; k < 4; k++) {
            int idx = tid + k * 256;
            int4 s = sidx4[idx];
            float4 v;
            v.x = (s.x >= 0) ? __ldg(src + s.x) : 0.0f;
            v.y = (s.y >= 0) ? __ldg(src + s.y) : 0.0f;
            v.z = (s.z >= 0) ? __ldg(src + s.z) : 0.0f;
            v.w = (s.w >= 0) ? __ldg(src + s.w) : 0.0f;
            dst[idx] = v;
        }
    }
}

// ---------------------------------------------------------------------------
extern "C" void kernel_launch(void* const* d_in, const int* in_sizes, int n_in,
                              void* d_out, int out_size) {
    const float* x    = (const float*)d_in[0];   // (8,512,64,64) f32
    const int*   mask = (const int*)d_in[1];     // (64,64) i32
    float* out = (float*)d_out;                  // (8,768,64,64) f32
    (void)in_sizes; (void)n_in; (void)out_size;

    fused_kernel<<<GRID_TOTAL, 256>>>(x, mask, out);
}

// round 13
// speedup vs baseline: 1.2665x; 1.2665x over previous
#include <cuda_runtime.h>
#include <cstdint>

// Problem: x (8,512,64,64) f32, mask (64,64) i32, out (8,768,64,64) f32
#define HW      4096
#define BATCH   8
#define CIN     512
#define C2      256
#define COUT    768

#define N_MERGED HW                // 4096 CTAs: argmax row=bid + copy plane=bid
#define N_SHIFT  (BATCH * C2)      // 2048 shift planes
#define GRID_TOTAL (N_MERGED + N_SHIFT)

// Scratch (allocation-free rule: __device__ globals)
__device__ int g_sidx[HW];         // flag[i] ? nb[i] : -1
__device__ int g_done    = 0;      // merged CTAs that published their row
__device__ int g_arrived = 0;      // shift CTAs past the spin

// ---------------------------------------------------------------------------
// threefry2x32 with key (0, 42), counters (x0=0, x1=c). JAX partitionable path:
// bits[i] = o0 ^ o1 with counter = i. ks = [0, 42, 0 ^ 42 ^ 0x1BD11BDA].
// Returns the 23-bit monotone proxy for uniform(float).
// ---------------------------------------------------------------------------
__device__ __forceinline__ unsigned threefry_bits(unsigned c) {
    const unsigned ks1 = 42u;
    const unsigned ks2 = 0x1BD11BDAu ^ 42u;   // 0x1BD11BF0
    unsigned x0 = 0u;          // counts_hi + ks0
    unsigned x1 = c + ks1;     // counts_lo + ks1
#define TF_RND(r) { x0 += x1; x1 = __funnelshift_l(x1, x1, (r)); x1 ^= x0; }
    TF_RND(13) TF_RND(15) TF_RND(26) TF_RND(6)
    x0 += ks1;  x1 += ks2 + 1u;
    TF_RND(17) TF_RND(29) TF_RND(16) TF_RND(24)
    x0 += ks2;  x1 += 0u  + 2u;
    TF_RND(13) TF_RND(15) TF_RND(26) TF_RND(6)
    x0 += 0u;   x1 += ks1 + 3u;
    TF_RND(17) TF_RND(29) TF_RND(16) TF_RND(24)
    x0 += ks1;  x1 += ks2 + 4u;
    TF_RND(13) TF_RND(15) TF_RND(26) TF_RND(6)
    x0 += ks2;  x1 += 0u  + 5u;
#undef TF_RND
    return (x0 ^ x1) >> 9;
}

// ---------------------------------------------------------------------------
// Copy of plane `bid`: out[b, ch] = x[b, ch] for ch < 512.
// ---------------------------------------------------------------------------
__device__ __forceinline__ void do_copy(int bid, int tid,
                                        const float* __restrict__ x,
                                        float* __restrict__ out) {
    const int b  = bid >> 9;             // /512
    const int ch = bid & 511;
    const float4* __restrict__ src =
        (const float4*)(x + ((size_t)b * CIN + ch) * HW);
    float4* __restrict__ dst =
        (float4*)(out + ((size_t)b * COUT + ch) * HW);
#pragma unroll
    for (int k = 0; k < 4; k++) {
        int idx = tid + k * 256;
        dst[idx] = src[idx];
    }
}

// ---------------------------------------------------------------------------
// Argmax for row = bid; publishes g_sidx[row] and bumps g_done.
// ---------------------------------------------------------------------------
__device__ __forceinline__ void do_argmax(int row, int tid,
                                          const int* __restrict__ mask,
                                          unsigned* scnt, int* wred,
                                          unsigned long long* wmax) {
    const unsigned rowbase = (unsigned)row * (unsigned)HW;
    if (mask[row] > 0) {
        // ---- per-CTA ordered compaction: thread t owns cols [16t,16t+16) ----
        const int lane = tid & 31;
        const int warp = tid >> 5;
        const unsigned base = rowbase + (unsigned)(tid * 16);
        unsigned flags = 0;
        const int4* m4 = (const int4*)mask;
#pragma unroll
        for (int k = 0; k < 4; k++) {
            int4 v = m4[tid * 4 + k];
            if (v.x <= 0) flags |= 1u << (k * 4 + 0);
            if (v.y <= 0) flags |= 1u << (k * 4 + 1);
            if (v.z <= 0) flags |= 1u << (k * 4 + 2);
            if (v.w <= 0) flags |= 1u << (k * 4 + 3);
        }
        const int cnt = __popc(flags);
        int inc = cnt;
#pragma unroll
        for (int o = 1; o < 32; o <<= 1) {
            int v = __shfl_up_sync(0xFFFFFFFFu, inc, o);
            if (lane >= o) inc += v;
        }
        if (lane == 31) wred[warp] = inc;
        __syncthreads();
        if (tid < 32) {
            int v = (tid < 8) ? wred[tid] : 0;
#pragma unroll
            for (int o = 1; o < 8; o <<= 1) {
                int u = __shfl_up_sync(0xFFFFFFFFu, v, o);
                if (lane >= o) v += u;
            }
            if (tid < 8) wred[tid] = v;   // inclusive warp totals
        }
        __syncthreads();
        int pos = inc - cnt + (warp ? wred[warp - 1] : 0);
        const int m = wred[7];
#pragma unroll
        for (int k = 0; k < 16; k++) {
            if (flags & (1u << k)) scnt[pos++] = base + (unsigned)k;
        }
        __syncthreads();

        // ---- masked argmax over compacted counters ----
        unsigned bv = 0u;
        unsigned bc = rowbase + (unsigned)(HW - 1);  // phantom: loses always

        int t = tid;
        for (; t + 256 < m; t += 512) {      // two independent chains
            unsigned c0 = scnt[t];
            unsigned c1 = scnt[t + 256];
            unsigned v0 = threefry_bits(c0);
            unsigned v1 = threefry_bits(c1);
            if (v0 > bv) { bv = v0; bc = c0; }   // c0 < c1: order preserved
            if (v1 > bv) { bv = v1; bc = c1; }
        }
        if (t < m) {
            unsigned c = scnt[t];
            unsigned v = threefry_bits(c);
            if (v > bv) { bv = v; bc = c; }
        }

        const int bj = (int)(bc - rowbase);
        unsigned long long key =
            ((unsigned long long)bv << 12) | (unsigned)(HW - 1 - bj);
#pragma unroll
        for (int o = 16; o > 0; o >>= 1) {
            unsigned long long other = __shfl_xor_sync(0xFFFFFFFFu, key, o);
            if (other > key) key = other;
        }
        if ((tid & 31) == 0) wmax[tid >> 5] = key;
        __syncthreads();
        if (tid < 32) {
            unsigned long long k2 = (tid < 8) ? wmax[tid] : 0ull;
#pragma unroll
            for (int o = 4; o > 0; o >>= 1) {
                unsigned long long other = __shfl_xor_sync(0xFFFFFFFFu, k2, o);
                if (other > k2) k2 = other;
            }
            if (tid == 0) {
                g_sidx[row] = (m == 0) ? 0 : (HW - 1 - (int)(k2 & 0xFFFu));
                __threadfence();
                atomicAdd(&g_done, 1);
            }
        }
    } else {
        // dead row: nb never consumed
        if (tid == 0) {
            g_sidx[row] = -1;
            __threadfence();
            atomicAdd(&g_done, 1);
        }
    }
}

// ---------------------------------------------------------------------------
// Single fused kernel.
//   bid < 4096       : merged CTA — copy plane + argmax row (staggered order).
//   bid >= 4096      : shift plane. Stage the 16 KB source plane into smem
//                      with coalesced float4 loads BEFORE the spin (overlaps
//                      the wait), then gather via LDS (bank conflicts ~3-4x,
//                      vs ~30 L1 wavefronts per scattered LDG.32).
// ---------------------------------------------------------------------------
__global__ void __launch_bounds__(256) fused_kernel(const float* __restrict__ x,
                                                    const int*   __restrict__ mask,
                                                    float*       __restrict__ out) {
    const int bid = blockIdx.x;
    const int tid = threadIdx.x;

    __shared__ union {
        struct {
            unsigned scnt[HW];     // rowbase + compacted column (ascending)
            int wred[8];
            unsigned long long wmax[8];
        } a;                       // argmax CTAs
        float plane[HW];           // shift CTAs: staged source plane
    } smem;

    if (bid < N_MERGED) {
        const bool copy_first = (bid & 1);
        if (copy_first) do_copy(bid, tid, x, out);
        do_argmax(bid, tid, mask, smem.a.scnt, smem.a.wred, smem.a.wmax);
        if (!copy_first) do_copy(bid, tid, x, out);
    } else {
        // ================= shift CTA =================
        const int p  = bid - N_MERGED;       // 0..2047
        const int b  = p >> 8;
        const int cc = p & 255;

        const float* __restrict__ src = x + ((size_t)b * CIN + C2 + cc) * HW;

        // stage source plane into smem (coalesced), independent of g_sidx
        {
            const float4* __restrict__ s4 = (const float4*)src;
            float4* __restrict__ p4 = (float4*)smem.plane;
#pragma unroll
            for (int k = 0; k < 4; k++) {
                int idx = tid + k * 256;
                p4[idx] = s4[idx];
            }
        }

        if (tid == 0) {
            // spin until every merged CTA has published its g_sidx entry.
            while (atomicAdd(&g_done, 0) != N_MERGED) __nanosleep(200);
            // the LAST shift CTA to pass the spin resets counters for the
            // next graph replay (all others already observed the condition).
            int a = atomicAdd(&g_arrived, 1);
            if (a == N_SHIFT - 1) {
                atomicExch(&g_done, 0);
                atomicExch(&g_arrived, 0);
            }
        }
        __syncthreads();   // plane staged + sidx published

        float* __restrict__ dstf = out + ((size_t)b * COUT + CIN + cc) * HW;
        float4* __restrict__ dst = (float4*)dstf;
        const int4* __restrict__ sidx4 = (const int4*)g_sidx;
#pragma unroll
        for (int k = 0; k < 4; k++) {
            int idx = tid + k * 256;
            int4 s = sidx4[idx];
            float4 v;
            v.x = (s.x >= 0) ? smem.plane[s.x] : 0.0f;
            v.y = (s.y >= 0) ? smem.plane[s.y] : 0.0f;
            v.z = (s.z >= 0) ? smem.plane[s.z] : 0.0f;
            v.w = (s.w >= 0) ? smem.plane[s.w] : 0.0f;
            dst[idx] = v;
        }
    }
}

// ---------------------------------------------------------------------------
extern "C" void kernel_launch(void* const* d_in, const int* in_sizes, int n_in,
                              void* d_out, int out_size) {
    const float* x    = (const float*)d_in[0];   // (8,512,64,64) f32
    const int*   mask = (const int*)d_in[1];     // (64,64) i32
    float* out = (float*)d_out;                  // (8,768,64,64) f32
    (void)in_sizes; (void)n_in; (void)out_size;

    fused_kernel<<<GRID_TOTAL, 256>>>(x, mask, out);
}